// round 10
// baseline (speedup 1.0000x reference)
#include <cuda_runtime.h>

#define TT 64
#define BB 256
#define DD 512

// pre-activations, K2-block-contiguous layout:
// g_pre2[bblk(32)][t(64)][bloc(8)][gate(4)][q(6)]
__device__ __align__(16) float g_pre2[TT * BB * 24];

// ---------------------------------------------------------------------------
// K1: pre[t,b,g,q] = inputs[t,b,:] @ Wg[:512,q] + bg[q] + theta_g[q]
// R2-K1 with ONE change: W padded to 32 floats/dd (gate g at offset 8g) so the
// per-d W read is LDS.128+LDS.64 (2 loads) instead of 3x LDS.64. W staged in
// 4 quarters (16KB) to fit the 48KB static smem limit. All else identical.
// ---------------------------------------------------------------------------
__global__ void __launch_bounds__(256, 1) k1_gemm(
    const float* __restrict__ X,
    const float* __restrict__ Wf, const float* __restrict__ bf,
    const float* __restrict__ Wi, const float* __restrict__ bi,
    const float* __restrict__ Wu, const float* __restrict__ bu,
    const float* __restrict__ Wo, const float* __restrict__ bo,
    const float* __restrict__ thf, const float* __restrict__ thi,
    const float* __restrict__ thu, const float* __restrict__ tho)
{
    __shared__ __align__(16) float Wph[128 * 32];  // K-quarter of W, [dd][g*8+q], 16KB
    __shared__ float Xsh[32 * 130];                // x tile transposed [d][row], 16.6KB

    const int tid  = threadIdx.x;
    const int warp = tid >> 5;
    const int lane = tid & 31;
    const int gate = warp & 3;
    const int rloc = ((warp >> 2) << 6) + (lane << 1);   // block-local row (even)
    const int rowbase = blockIdx.x << 7;

    const float* bg = (gate == 0) ? bf  : (gate == 1) ? bi  : (gate == 2) ? bu  : bo;
    const float* tg = (gate == 0) ? thf : (gate == 1) ? thi : (gate == 2) ? thu : tho;

    // packed accumulators: (q0,q1) (q2,q3) (q4,q5) for each of 2 rows
    unsigned long long a0[3], a1[3];
#pragma unroll
    for (int p = 0; p < 3; p++) {
        float blo = __ldg(bg + 2 * p + 0) + __ldg(tg + 2 * p + 0);
        float bhi = __ldg(bg + 2 * p + 1) + __ldg(tg + 2 * p + 1);
        unsigned long long bp;
        asm("mov.b64 %0, {%1, %2};" : "=l"(bp) : "f"(blo), "f"(bhi));
        a0[p] = bp;
        a1[p] = bp;
    }

    const int cc = tid & 7;   // d-group for staging
    const int rr = tid >> 3;  // row for staging

    for (int kq = 0; kq < 4; kq++) {
        __syncthreads();  // prior compute done before Wph overwrite
        // stage W quarter kq (128 dd x 24 useful cols) into padded [dd][32]
#pragma unroll
        for (int k = 0; k < 12; k++) {
            int idx = tid + (k << 8);          // 0..3071 == dd*24 + col
            int dd  = idx / 24;
            int col = idx - dd * 24;
            int g2  = col / 6;
            int q2  = col - g2 * 6;
            const float* Ws = (g2 == 0) ? Wf : (g2 == 1) ? Wi : (g2 == 2) ? Wu : Wo;
            Wph[(dd << 5) + (g2 << 3) + q2] = Ws[((kq << 7) + dd) * 6 + q2];
        }
        for (int tile = 0; tile < 4; tile++) {
            const int d0 = (kq << 7) + (tile << 5);
            __syncthreads();  // Wph visible (tile 0); Xsh free to overwrite
#pragma unroll
            for (int p = 0; p < 4; p++) {
                int r = rr + (p << 5);
                const float4 v = *reinterpret_cast<const float4*>(
                    X + (size_t)(rowbase + r) * DD + d0 + (cc << 2));
                Xsh[((cc << 2) + 0) * 130 + r] = v.x;
                Xsh[((cc << 2) + 1) * 130 + r] = v.y;
                Xsh[((cc << 2) + 2) * 130 + r] = v.z;
                Xsh[((cc << 2) + 3) * 130 + r] = v.w;
            }
            __syncthreads();
#pragma unroll
            for (int d = 0; d < 32; d++) {
                const int dd = (tile << 5) + d;        // local within quarter
                const ulonglong2 wAB = *reinterpret_cast<const ulonglong2*>(
                    &Wph[(dd << 5) + (gate << 3)]);    // LDS.128: (w01, w23)
                const unsigned long long w01 = wAB.x;
                const unsigned long long w23 = wAB.y;
                const unsigned long long w45 = *reinterpret_cast<const unsigned long long*>(
                    &Wph[(dd << 5) + (gate << 3) + 4]); // LDS.64
                const float2 x2 = *reinterpret_cast<const float2*>(&Xsh[d * 130 + rloc]);
                unsigned long long xr0, xr1;
                asm("mov.b64 %0, {%1, %1};" : "=l"(xr0) : "f"(x2.x));
                asm("mov.b64 %0, {%1, %1};" : "=l"(xr1) : "f"(x2.y));
                asm("fma.rn.f32x2 %0, %1, %2, %0;" : "+l"(a0[0]) : "l"(w01), "l"(xr0));
                asm("fma.rn.f32x2 %0, %1, %2, %0;" : "+l"(a0[1]) : "l"(w23), "l"(xr0));
                asm("fma.rn.f32x2 %0, %1, %2, %0;" : "+l"(a0[2]) : "l"(w45), "l"(xr0));
                asm("fma.rn.f32x2 %0, %1, %2, %0;" : "+l"(a1[0]) : "l"(w01), "l"(xr1));
                asm("fma.rn.f32x2 %0, %1, %2, %0;" : "+l"(a1[1]) : "l"(w23), "l"(xr1));
                asm("fma.rn.f32x2 %0, %1, %2, %0;" : "+l"(a1[2]) : "l"(w45), "l"(xr1));
            }
        }
    }

    // row = t*BB + b ; store to K2-block-contiguous layout
    const int t = rowbase >> 8;
    const int b = (rowbase & 255) + rloc;       // even; b+1 shares b>>3
    float* dst = g_pre2 + ((size_t)((b >> 3) * 64 + t) * 192) + (b & 7) * 24 + gate * 6;
    unsigned long long* d64 = reinterpret_cast<unsigned long long*>(dst);
    d64[0] = a0[0]; d64[1] = a0[1]; d64[2] = a0[2];
    unsigned long long* e64 = reinterpret_cast<unsigned long long*>(dst + 24);
    e64[0] = a1[0]; e64[1] = a1[1]; e64[2] = a1[2];
}

// tanh via CF rational x*(10395+1260 s+21 s^2)/(10395+4725 s+210 s^2+s^3),
// one rcp; err <= ~2e-5 for |x| <= 2.2, <= ~1e-7 for |x| <= 1.
__device__ __forceinline__ float tanh_rat(float x) {
    float s = x * x;
    float num = fmaf(s, fmaf(s, 21.0f, 1260.0f), 10395.0f);
    float den = fmaf(s, fmaf(s, s + 210.0f, 4725.0f), 10395.0f);
    float r;
    asm("rcp.approx.f32 %0, %1;" : "=f"(r) : "f"(den));
    return x * num * r;
}

// ---------------------------------------------------------------------------
// K2: LSTM scan — R9 kernel with ONE change: the gate path uses tanh_rat
// (single MUFU stage) instead of exp+div (two serial MUFU stages).
// grid 32 x 128; warps stage 48KB of pre; warp 0 scans.
// lane = (batch-in-block<<2)|gate ; h,c replicated across the 4 gate lanes.
// ---------------------------------------------------------------------------
__global__ void __launch_bounds__(128, 1) k2_scan(
    const float* __restrict__ Wf, const float* __restrict__ Wi,
    const float* __restrict__ Wu, const float* __restrict__ Wo,
    float* __restrict__ out)
{
    __shared__ float ps[TT * 192];    // 48KB : [t][bloc(8)][gate][q]

    const int tid = threadIdx.x;

    // cooperative bulk load (coalesced float4)
    {
        const float4* src = reinterpret_cast<const float4*>(g_pre2 + (size_t)blockIdx.x * (TT * 192));
        float4* dst = reinterpret_cast<float4*>(ps);
#pragma unroll
        for (int i = 0; i < (TT * 192) / 4 / 128; i++)
            dst[tid + i * 128] = src[tid + i * 128];
    }
    __syncthreads();
    if (tid >= 32) return;

    const int lane = tid;
    const int g    = lane & 3;
    const int bl   = lane >> 2;
    const int b    = (blockIdx.x << 3) + bl;
    const float* Wg = (g == 0) ? Wf : (g == 1) ? Wi : (g == 2) ? Wu : Wo;

    float Wh[36];
#pragma unroll
    for (int j = 0; j < 6; j++)
#pragma unroll
        for (int q = 0; q < 6; q++)
            Wh[j * 6 + q] = __ldg(Wg + (DD + j) * 6 + q);

    float h[6], c[6];
#pragma unroll
    for (int q = 0; q < 6; q++) { h[q] = 0.0f; c[q] = 0.0f; }

    const float* pb = ps + bl * 24 + g * 6;
    const unsigned mask = 0xffffffffu;
    const int qb = lane & ~3;
    const bool isU = (g == 2);
    const float amul = isU ? 1.0f : 0.5f;   // tanh argument scale

#pragma unroll 2
    for (int t = 0; t < TT; t++) {
        const float2 p0 = *reinterpret_cast<const float2*>(pb + t * 192 + 0);
        const float2 p1 = *reinterpret_cast<const float2*>(pb + t * 192 + 2);
        const float2 p2 = *reinterpret_cast<const float2*>(pb + t * 192 + 4);
        float p[6] = { p0.x, p0.y, p1.x, p1.y, p2.x, p2.y };

        // a[q] = p[q] + h @ Wh  -- two parallel partials, then add
        float a[6];
#pragma unroll
        for (int q = 0; q < 6; q++) {
            float u0 = fmaf(h[0], Wh[0 * 6 + q], fmaf(h[1], Wh[1 * 6 + q], fmaf(h[2], Wh[2 * 6 + q], p[q])));
            float u1 = fmaf(h[3], Wh[3 * 6 + q], fmaf(h[4], Wh[4 * 6 + q], h[5] * Wh[5 * 6 + q]));
            a[q] = u0 + u1;
        }

        float z[6];
#pragma unroll
        for (int q = 0; q < 6; q++) z[q] = __cosf(a[q]);

        // prefix products (tree form)
        float z01 = z[0] * z[1];
        float z23 = z[2] * z[3];
        float z45 = z[4] * z[5];
        float w[6];
        w[1] = z01;
        w[2] = z01 * z[2];
        w[3] = z01 * z23;
        w[4] = w[3] * z[4];
        w[5] = w[3] * z45;
        w[0] = z[1] * (z23 * z45);

        // f,i,o: sigmoid(w) = 0.5 + 0.5*tanh(w/2) ; u: tanh(w)
        // single MUFU stage (rcp inside tanh_rat), |arg| <= 1
        float v[6];
#pragma unroll
        for (int q = 0; q < 6; q++) {
            float tr = tanh_rat(amul * w[q]);
            v[q] = isU ? tr : fmaf(0.5f, tr, 0.5f);
        }

        // gather the 4 gates' values and update (replicated)
#pragma unroll
        for (int q = 0; q < 6; q++) {
            float fq = __shfl_sync(mask, v[q], qb + 0);
            float iq = __shfl_sync(mask, v[q], qb + 1);
            float uq = __shfl_sync(mask, v[q], qb + 2);
            float oq = __shfl_sync(mask, v[q], qb + 3);
            float cn = fmaf(fq, c[q], iq * uq);
            c[q] = cn;
            h[q] = oq * tanh_rat(cn);          // |cn| <= 2.08 guaranteed
        }

        if (g == 0) {
            float* o0 = out + ((size_t)t * BB + b) * 6;
            *reinterpret_cast<float2*>(o0 + 0) = make_float2(h[0], h[1]);
            *reinterpret_cast<float2*>(o0 + 2) = make_float2(h[2], h[3]);
            *reinterpret_cast<float2*>(o0 + 4) = make_float2(h[4], h[5]);
        }
    }

    if (g == 0) {
        float* hx = out + (size_t)TT * BB * 6 + (size_t)b * 6;
        float* cx = hx + BB * 6;
        *reinterpret_cast<float2*>(hx + 0) = make_float2(h[0], h[1]);
        *reinterpret_cast<float2*>(hx + 2) = make_float2(h[2], h[3]);
        *reinterpret_cast<float2*>(hx + 4) = make_float2(h[4], h[5]);
        *reinterpret_cast<float2*>(cx + 0) = make_float2(c[0], c[1]);
        *reinterpret_cast<float2*>(cx + 2) = make_float2(c[2], c[3]);
        *reinterpret_cast<float2*>(cx + 4) = make_float2(c[4], c[5]);
    }
}

extern "C" void kernel_launch(void* const* d_in, const int* in_sizes, int n_in,
                              void* d_out, int out_size)
{
    const float* X   = (const float*)d_in[0];
    const float* Wf  = (const float*)d_in[1];
    const float* bf  = (const float*)d_in[2];
    const float* Wi  = (const float*)d_in[3];
    const float* bi  = (const float*)d_in[4];
    const float* Wu  = (const float*)d_in[5];
    const float* bu  = (const float*)d_in[6];
    const float* Wo  = (const float*)d_in[7];
    const float* bo  = (const float*)d_in[8];
    const float* thf = (const float*)d_in[9];
    const float* thi = (const float*)d_in[10];
    const float* thu = (const float*)d_in[11];
    const float* tho = (const float*)d_in[12];
    float* out = (float*)d_out;

    k1_gemm<<<128, 256>>>(X, Wf, bf, Wi, bi, Wu, bu, Wo, bo, thf, thi, thu, tho);
    k2_scan<<<32, 128>>>(Wf, Wi, Wu, Wo, out);
}

// round 11
// speedup vs baseline: 1.0993x; 1.0993x over previous
#include <cuda_runtime.h>

#define TT 64
#define BB 256
#define DD 512

// pre-activations, K2-block-contiguous layout:
// g_pre2[bblk(32)][t(64)][bloc(8)][gate(4)][q(6)]
__device__ __align__(16) float g_pre2[TT * BB * 24];

// ---------------------------------------------------------------------------
// K1: pre[t,b,g,q] = inputs[t,b,:] @ Wg[:512,q] + bg[q] + theta_g[q]
// EXACT R2 kernel (best measured K1). grid 128 x 256; warp w: gate = w&3,
// row-half = w>>2; lane owns 2 adjacent rows; packed fma.rn.f32x2 accumulators.
// ---------------------------------------------------------------------------
__global__ void __launch_bounds__(256, 1) k1_gemm(
    const float* __restrict__ X,
    const float* __restrict__ Wf, const float* __restrict__ bf,
    const float* __restrict__ Wi, const float* __restrict__ bi,
    const float* __restrict__ Wu, const float* __restrict__ bu,
    const float* __restrict__ Wo, const float* __restrict__ bo,
    const float* __restrict__ thf, const float* __restrict__ thi,
    const float* __restrict__ thu, const float* __restrict__ tho)
{
    __shared__ float Wph[256 * 24];   // K-half of W, [dd][g*6+q]
    __shared__ float Xsh[32 * 130];   // x tile transposed [d][row]

    const int tid  = threadIdx.x;
    const int warp = tid >> 5;
    const int lane = tid & 31;
    const int gate = warp & 3;
    const int rloc = ((warp >> 2) << 6) + (lane << 1);   // block-local row (even)
    const int rowbase = blockIdx.x << 7;

    const float* bg = (gate == 0) ? bf  : (gate == 1) ? bi  : (gate == 2) ? bu  : bo;
    const float* tg = (gate == 0) ? thf : (gate == 1) ? thi : (gate == 2) ? thu : tho;

    unsigned long long a0[3], a1[3];
#pragma unroll
    for (int p = 0; p < 3; p++) {
        float blo = __ldg(bg + 2 * p + 0) + __ldg(tg + 2 * p + 0);
        float bhi = __ldg(bg + 2 * p + 1) + __ldg(tg + 2 * p + 1);
        unsigned long long bp;
        asm("mov.b64 %0, {%1, %2};" : "=l"(bp) : "f"(blo), "f"(bhi));
        a0[p] = bp;
        a1[p] = bp;
    }

    const int cc = tid & 7;   // d-group for staging
    const int rr = tid >> 3;  // row for staging

    for (int kh = 0; kh < 2; kh++) {
        __syncthreads();
#pragma unroll
        for (int k = 0; k < 24; k++) {
            int idx = tid + (k << 8);          // dd*24 + col
            int dd  = idx / 24;
            int col = idx - dd * 24;
            int g2  = col / 6;
            int q2  = col - g2 * 6;
            const float* Ws = (g2 == 0) ? Wf : (g2 == 1) ? Wi : (g2 == 2) ? Wu : Wo;
            Wph[idx] = Ws[((kh << 8) + dd) * 6 + q2];
        }
        for (int tile = 0; tile < 8; tile++) {
            const int d0 = (kh << 8) + (tile << 5);
            __syncthreads();
#pragma unroll
            for (int p = 0; p < 4; p++) {
                int r = rr + (p << 5);
                const float4 v = *reinterpret_cast<const float4*>(
                    X + (size_t)(rowbase + r) * DD + d0 + (cc << 2));
                Xsh[((cc << 2) + 0) * 130 + r] = v.x;
                Xsh[((cc << 2) + 1) * 130 + r] = v.y;
                Xsh[((cc << 2) + 2) * 130 + r] = v.z;
                Xsh[((cc << 2) + 3) * 130 + r] = v.w;
            }
            __syncthreads();
#pragma unroll
            for (int d = 0; d < 32; d++) {
                const int dd = (tile << 5) + d;
                const unsigned long long* wp =
                    reinterpret_cast<const unsigned long long*>(&Wph[dd * 24 + gate * 6]);
                const unsigned long long w01 = wp[0];
                const unsigned long long w23 = wp[1];
                const unsigned long long w45 = wp[2];
                const float2 x2 = *reinterpret_cast<const float2*>(&Xsh[d * 130 + rloc]);
                unsigned long long xr0, xr1;
                asm("mov.b64 %0, {%1, %1};" : "=l"(xr0) : "f"(x2.x));
                asm("mov.b64 %0, {%1, %1};" : "=l"(xr1) : "f"(x2.y));
                asm("fma.rn.f32x2 %0, %1, %2, %0;" : "+l"(a0[0]) : "l"(w01), "l"(xr0));
                asm("fma.rn.f32x2 %0, %1, %2, %0;" : "+l"(a0[1]) : "l"(w23), "l"(xr0));
                asm("fma.rn.f32x2 %0, %1, %2, %0;" : "+l"(a0[2]) : "l"(w45), "l"(xr0));
                asm("fma.rn.f32x2 %0, %1, %2, %0;" : "+l"(a1[0]) : "l"(w01), "l"(xr1));
                asm("fma.rn.f32x2 %0, %1, %2, %0;" : "+l"(a1[1]) : "l"(w23), "l"(xr1));
                asm("fma.rn.f32x2 %0, %1, %2, %0;" : "+l"(a1[2]) : "l"(w45), "l"(xr1));
            }
        }
    }

    const int t = rowbase >> 8;
    const int b = (rowbase & 255) + rloc;       // even; b+1 shares b>>3
    float* dst = g_pre2 + ((size_t)((b >> 3) * 64 + t) * 192) + (b & 7) * 24 + gate * 6;
    unsigned long long* d64 = reinterpret_cast<unsigned long long*>(dst);
    d64[0] = a0[0]; d64[1] = a0[1]; d64[2] = a0[2];
    unsigned long long* e64 = reinterpret_cast<unsigned long long*>(dst + 24);
    e64[0] = a1[0]; e64[1] = a1[1]; e64[2] = a1[2];
}

// tanh via CF rational, one rcp; err <= ~2e-5 for |x| <= 2.2 (|c| <= 2.08).
__device__ __forceinline__ float tanh_rat(float x) {
    float s = x * x;
    float num = fmaf(s, fmaf(s, 21.0f, 1260.0f), 10395.0f);
    float den = fmaf(s, fmaf(s, s + 210.0f, 4725.0f), 10395.0f);
    float r;
    asm("rcp.approx.f32 %0, %1;" : "=f"(r) : "f"(den));
    return x * num * r;
}

// ---------------------------------------------------------------------------
// K2: LSTM scan, wire-split. grid 32 x 128; all threads stage 48KB; warps 0-1
// scan 4 batches each. lane = bl*8 + gate*2 + qh; each lane owns 3 wires
// (q = 3qh..3qh+2). z and h exchanged with partner lane (xor 1); gate values
// gathered across the 4 gate lanes (same qh). c,h replicated across gates.
// Per-warp instructions/step ~118 vs 174 in the 6-wire version.
// ---------------------------------------------------------------------------
__global__ void __launch_bounds__(128, 1) k2_scan(
    const float* __restrict__ Wf, const float* __restrict__ Wi,
    const float* __restrict__ Wu, const float* __restrict__ Wo,
    float* __restrict__ out)
{
    __shared__ float ps[TT * 192];    // 48KB : [t][bloc(8)][gate][q]

    const int tid = threadIdx.x;

    {
        const float4* src = reinterpret_cast<const float4*>(g_pre2 + (size_t)blockIdx.x * (TT * 192));
        float4* dst = reinterpret_cast<float4*>(ps);
#pragma unroll
        for (int i = 0; i < (TT * 192) / 4 / 128; i++)
            dst[tid + i * 128] = src[tid + i * 128];
    }
    __syncthreads();
    if (tid >= 64) return;

    const int lane = tid & 31;
    const int wrp  = tid >> 5;            // 0 or 1
    const int qh   = lane & 1;            // wire half
    const int g    = (lane >> 1) & 3;     // gate
    const int bl   = lane >> 3;           // batch within warp (0..3)
    const int bloc = (wrp << 2) + bl;     // batch within block (0..7)
    const int b    = (blockIdx.x << 3) + bloc;
    const int q0   = 3 * qh;
    const float* Wg = (g == 0) ? Wf : (g == 1) ? Wi : (g == 2) ? Wu : Wo;

    // recurrent weights for own 3 wires: Whk[k][j] = Wg[512+k][q0+j]
    float Whk[6][3];
#pragma unroll
    for (int k = 0; k < 6; k++)
#pragma unroll
        for (int j = 0; j < 3; j++)
            Whk[k][j] = __ldg(Wg + (DD + k) * 6 + q0 + j);

    float h6[6];
#pragma unroll
    for (int k = 0; k < 6; k++) h6[k] = 0.0f;
    float c[3] = { 0.0f, 0.0f, 0.0f };

    const float* pb = ps + bloc * 24 + g * 6 + q0;
    const unsigned mask = 0xffffffffu;
    const int lb  = (lane & 24) | qh;     // gate-0 lane of this (batch, qh)
    const bool isU = (g == 2);
    const float cmul = isU ? -2.0f : -1.0f;
    const bool store = (g == 0);

#pragma unroll 2
    for (int t = 0; t < TT; t++) {
        const float p0 = pb[t * 192 + 0];
        const float p1 = pb[t * 192 + 1];
        const float p2 = pb[t * 192 + 2];

        // a[j] = p[j] + h6 @ Whk (two parallel partials per wire)
        float a[3];
        {
            float pj[3] = { p0, p1, p2 };
#pragma unroll
            for (int j = 0; j < 3; j++) {
                float u0 = fmaf(h6[0], Whk[0][j], fmaf(h6[1], Whk[1][j], fmaf(h6[2], Whk[2][j], pj[j])));
                float u1 = fmaf(h6[3], Whk[3][j], fmaf(h6[4], Whk[4][j], h6[5] * Whk[5][j]));
                a[j] = u0 + u1;
            }
        }

        float z0 = __cosf(a[0]);
        float z1 = __cosf(a[1]);
        float z2 = __cosf(a[2]);

        // exchange with partner lane to assemble all 6 z (q-ordered)
        float zp0 = __shfl_xor_sync(mask, z0, 1);
        float zp1 = __shfl_xor_sync(mask, z1, 1);
        float zp2 = __shfl_xor_sync(mask, z2, 1);
        float zA0 = qh ? zp0 : z0;   // q0
        float zA1 = qh ? zp1 : z1;   // q1
        float zA2 = qh ? zp2 : z2;   // q2
        float zB0 = qh ? z0 : zp0;   // q3
        float zB1 = qh ? z1 : zp1;   // q4
        float zB2 = qh ? z2 : zp2;   // q5

        // entanglement products; own 3 selected by qh
        float z01 = zA0 * zA1;
        float z23 = zA2 * zB0;
        float z45 = zB1 * zB2;
        float w3  = z01 * z23;
        float wv0 = qh ? w3        : zA1 * (z23 * z45);   // w3 : w0
        float wv1 = qh ? w3 * zB1  : z01;                 // w4 : w1
        float wv2 = qh ? w3 * z45  : z01 * zA2;           // w5 : w2

        // gate value (exp-based sigmoid; u: tanh = 2*sigmoid(2w)-1)
        float v0, v1, v2;
        {
            float e0 = __expf(cmul * wv0);
            float e1 = __expf(cmul * wv1);
            float e2 = __expf(cmul * wv2);
            float s0 = __fdividef(1.0f, 1.0f + e0);
            float s1 = __fdividef(1.0f, 1.0f + e1);
            float s2 = __fdividef(1.0f, 1.0f + e2);
            v0 = isU ? fmaf(2.0f, s0, -1.0f) : s0;
            v1 = isU ? fmaf(2.0f, s1, -1.0f) : s1;
            v2 = isU ? fmaf(2.0f, s2, -1.0f) : s2;
        }

        // gather f,i,u,o for own 3 wires (lanes lb, lb+2, lb+4, lb+6)
        float hq[3];
#pragma unroll
        for (int j = 0; j < 3; j++) {
            float vj = (j == 0) ? v0 : (j == 1) ? v1 : v2;
            float fq = __shfl_sync(mask, vj, lb + 0);
            float iq = __shfl_sync(mask, vj, lb + 2);
            float uq = __shfl_sync(mask, vj, lb + 4);
            float oq = __shfl_sync(mask, vj, lb + 6);
            float cn = fmaf(fq, c[j], iq * uq);
            c[j] = cn;
            hq[j] = oq * tanh_rat(cn);     // |cn| <= 2.08 guaranteed
        }

        if (store) {
            float* o0 = out + ((size_t)t * BB + b) * 6 + q0;
            o0[0] = hq[0]; o0[1] = hq[1]; o0[2] = hq[2];
        }

        // exchange h with partner to rebuild h6 for next step's dot
        float hp0 = __shfl_xor_sync(mask, hq[0], 1);
        float hp1 = __shfl_xor_sync(mask, hq[1], 1);
        float hp2 = __shfl_xor_sync(mask, hq[2], 1);
        h6[0] = qh ? hp0 : hq[0];
        h6[1] = qh ? hp1 : hq[1];
        h6[2] = qh ? hp2 : hq[2];
        h6[3] = qh ? hq[0] : hp0;
        h6[4] = qh ? hq[1] : hp1;
        h6[5] = qh ? hq[2] : hp2;
    }

    if (store) {
        float* hx = out + (size_t)TT * BB * 6 + (size_t)b * 6 + q0;
        float* cx = hx + BB * 6;
        hx[0] = qh ? h6[3] : h6[0];
        hx[1] = qh ? h6[4] : h6[1];
        hx[2] = qh ? h6[5] : h6[2];
        cx[0] = c[0]; cx[1] = c[1]; cx[2] = c[2];
    }
}

extern "C" void kernel_launch(void* const* d_in, const int* in_sizes, int n_in,
                              void* d_out, int out_size)
{
    const float* X   = (const float*)d_in[0];
    const float* Wf  = (const float*)d_in[1];
    const float* bf  = (const float*)d_in[2];
    const float* Wi  = (const float*)d_in[3];
    const float* bi  = (const float*)d_in[4];
    const float* Wu  = (const float*)d_in[5];
    const float* bu  = (const float*)d_in[6];
    const float* Wo  = (const float*)d_in[7];
    const float* bo  = (const float*)d_in[8];
    const float* thf = (const float*)d_in[9];
    const float* thi = (const float*)d_in[10];
    const float* thu = (const float*)d_in[11];
    const float* tho = (const float*)d_in[12];
    float* out = (float*)d_out;

    k1_gemm<<<128, 256>>>(X, Wf, bf, Wi, bi, Wu, bu, Wo, bo, thf, thi, thu, tho);
    k2_scan<<<32, 128>>>(Wf, Wi, Wu, Wo, out);
}